// round 16
// baseline (speedup 1.0000x reference)
#include <cuda_runtime.h>
#include <cuda_bf16.h>
#include <cuda_fp16.h>
#include <cstdint>
#include <cstddef>

// Problem constants
#define BB 2
#define TT 2048
#define DD 2048
#define HQ 16
#define HKV 8
#define HD 128
#define MROWS (BB*TT)   // 4096

typedef __nv_bfloat16 bf16;

// log2(e)/sqrt(128)
#define QSCALE 0.12752551164384637f
#define WSCALE 256.0f
#define INV256 0.00390625f

// ---------------- scratch (static device globals) ---------------------------
__device__ __half g_xh [(size_t)MROWS*DD];                      // single plane
__device__ __half g_Wqh[(size_t)HQ*HD*DD];                      // single plane
__device__ __half g_Wkh[(size_t)HKV*HD*DD];                     // single plane
__device__ __half g_Wvh[(size_t)HKV*HD*DD];                     // single plane
__device__ __half g_Woh[(size_t)DD*HQ*HD];                      // single plane
__device__ bf16 g_Qh [(size_t)BB*HQ*TT*HD],  g_Ql [(size_t)BB*HQ*TT*HD];
__device__ bf16 g_Kh [(size_t)BB*HKV*TT*HD], g_Kl [(size_t)BB*HKV*TT*HD];
__device__ __half g_Vh [(size_t)MROWS*HKV*HD];                  // single plane
__device__ __half g_ctxh[(size_t)MROWS*HQ*HD];                  // single plane

// ---------------- PTX helpers ------------------------------------------------
__device__ __forceinline__ void ldsm4(uint32_t* r, uint32_t a) {
    asm volatile("ldmatrix.sync.aligned.m8n8.x4.shared.b16 {%0,%1,%2,%3}, [%4];\n"
        : "=r"(r[0]), "=r"(r[1]), "=r"(r[2]), "=r"(r[3]) : "r"(a));
}
__device__ __forceinline__ void ldsm4t(uint32_t* r, uint32_t a) {
    asm volatile("ldmatrix.sync.aligned.m8n8.x4.trans.shared.b16 {%0,%1,%2,%3}, [%4];\n"
        : "=r"(r[0]), "=r"(r[1]), "=r"(r[2]), "=r"(r[3]) : "r"(a));
}
__device__ __forceinline__ void mma16816(float* c, const uint32_t* a, const uint32_t* b) {
    asm volatile("mma.sync.aligned.m16n8k16.row.col.f32.bf16.bf16.f32 "
        "{%0,%1,%2,%3}, {%4,%5,%6,%7}, {%8,%9}, {%0,%1,%2,%3};\n"
        : "+f"(c[0]), "+f"(c[1]), "+f"(c[2]), "+f"(c[3])
        : "r"(a[0]), "r"(a[1]), "r"(a[2]), "r"(a[3]), "r"(b[0]), "r"(b[1]));
}
__device__ __forceinline__ void mma16816h(float* c, const uint32_t* a, const uint32_t* b) {
    asm volatile("mma.sync.aligned.m16n8k16.row.col.f32.f16.f16.f32 "
        "{%0,%1,%2,%3}, {%4,%5,%6,%7}, {%8,%9}, {%0,%1,%2,%3};\n"
        : "+f"(c[0]), "+f"(c[1]), "+f"(c[2]), "+f"(c[3])
        : "r"(a[0]), "r"(a[1]), "r"(a[2]), "r"(a[3]), "r"(b[0]), "r"(b[1]));
}
__device__ __forceinline__ void cp_async16(uint32_t dst, const void* src) {
    asm volatile("cp.async.cg.shared.global [%0], [%1], 16;\n" :: "r"(dst), "l"(src));
}
__device__ __forceinline__ void cp_commit() {
    asm volatile("cp.async.commit_group;\n" ::: "memory");
}
__device__ __forceinline__ uint32_t packbf(float a, float b) {
    __nv_bfloat162 t = __floats2bfloat162_rn(a, b);
    return *(uint32_t*)&t;
}
__device__ __forceinline__ uint32_t packh(float a, float b) {
    __half2 t = __floats2half2_rn(a, b);
    return *(uint32_t*)&t;
}
__device__ __forceinline__ void split2(float a, float b, uint32_t& h, uint32_t& l) {
    bf16 ha = __float2bfloat16(a), hb = __float2bfloat16(b);
    h = ((uint32_t)__bfloat16_as_ushort(hb) << 16) | (uint32_t)__bfloat16_as_ushort(ha);
    l = packbf(a - __bfloat162float(ha), b - __bfloat162float(hb));
}

// ---------------- fused operand conversion (single launch) -------------------
__global__ __launch_bounds__(256) void split_all_kernel(
    const float4* __restrict__ x,  const float4* __restrict__ Wq,
    const float4* __restrict__ Wk, const float4* __restrict__ Wv,
    const float4* __restrict__ Wo,
    __half* __restrict__ xh,
    __half* __restrict__ Wqh, __half* __restrict__ Wkh,
    __half* __restrict__ Wvh, __half* __restrict__ Woh)
{
    int blk = blockIdx.x;
    if (blk < 8192) {
        int i = blk*256 + threadIdx.x;
        float4 v = x[i];
        *(uint2*)(xh + (size_t)i*4) = make_uint2(packh(v.x, v.y), packh(v.z, v.w));
        return;
    }
    blk -= 8192;
    const float4* in; __half* out;
    if (blk < 4096)      {                in = Wq; out = Wqh; }
    else if (blk < 6144) { blk -= 4096;   in = Wk; out = Wkh; }
    else if (blk < 8192) { blk -= 6144;   in = Wv; out = Wvh; }
    else                 { blk -= 8192;   in = Wo; out = Woh; }
    int i = blk*256 + threadIdx.x;
    float4 v = in[i];
    *(uint2*)(out + (size_t)i*4) =
        make_uint2(packh(v.x*WSCALE, v.y*WSCALE), packh(v.z*WSCALE, v.w*WSCALE));
}

// ---------------- GEMM core (fp16 1-mma, CTA 64x128, BK=64, 2-stage) ---------
// 8 warps as 2(M) x 4(N); warp tile 32x32; 3 CTAs/SM.
#define BKC 64
#define PAD 72
#define AELE (64*PAD)           // 4608 fp16
#define BELE (128*PAD)          // 9216 fp16
#define STGE (AELE + BELE)      // 13824 fp16 = 27648 B
#define GSMEM2 (2*STGE*2)       // 55296 bytes

#define GEMM_PROLOGUE()                                                         \
    const int tid  = threadIdx.x;                                               \
    const int lane = tid & 31, wid = tid >> 5;                                  \
    const int wm = (wid & 1) * 32;                                              \
    const int wn = (wid >> 1) * 32;                                             \
    const int mrow = tid >> 3;                                                  \
    const int ccol = (tid & 7) * 8;                                             \
    const int r_   = lane & 7, blk_ = lane >> 3;                                \
    const int a_row = ((blk_ & 1) << 3) + r_;                                   \
    const int a_col = (blk_ >> 1) << 3;                                         \
    const int b_row = ((blk_ >> 1) << 3) + r_;                                  \
    const int b_col = (blk_ & 1) << 3;                                          \
    float acc[2][4][4];                                                         \
    _Pragma("unroll") for (int i = 0; i < 2; i++)                               \
    _Pragma("unroll") for (int j = 0; j < 4; j++)                               \
    _Pragma("unroll") for (int k = 0; k < 4; k++) acc[i][j][k] = 0.f;

#define ISSUE1(it, stage) do {                                                  \
    const int k0_ = (it) * BKC;                                                 \
    uint32_t sst_ = sbase + (uint32_t)(stage) * (STGE * 2);                     \
    _Pragma("unroll")                                                           \
    for (int rg_ = 0; rg_ < 2; rg_++) {                                         \
        int m_ = mrow + rg_ * 32;                                               \
        cp_async16(sst_ + (uint32_t)((m_*PAD + ccol) * 2),                      \
                   gA + (size_t)(row0 + m_) * K + k0_ + ccol);                  \
    }                                                                           \
    _Pragma("unroll")                                                           \
    for (int rg_ = 0; rg_ < 4; rg_++) {                                         \
        int n_ = mrow + rg_ * 32;                                               \
        cp_async16(sst_ + (uint32_t)((AELE + n_*PAD + ccol) * 2),               \
                   gB0 + (size_t)(col0 + n_) * K + k0_ + ccol);                 \
    }                                                                           \
} while (0)

#define GEMM_MAINLOOP1()                                                        \
    ISSUE1(0, 0);                                                               \
    cp_commit();                                                                \
    for (int it = 0; it < niter; it++) {                                        \
        if (it + 1 < niter) {                                                   \
            ISSUE1(it + 1, (it + 1) & 1);                                       \
            cp_commit();                                                        \
            asm volatile("cp.async.wait_group 1;\n" ::: "memory");              \
        } else {                                                                \
            asm volatile("cp.async.wait_group 0;\n" ::: "memory");              \
        }                                                                       \
        __syncthreads();                                                        \
        const uint32_t sst = sbase + (uint32_t)(it & 1) * (STGE * 2);           \
        _Pragma("unroll")                                                       \
        for (int ks = 0; ks < 4; ks++) {                                        \
            const int kofs = ks * 16;                                           \
            uint32_t a_[2][4], bh_[2][4];                                       \
            _Pragma("unroll")                                                   \
            for (int mt = 0; mt < 2; mt++)                                      \
                ldsm4(a_[mt], sst + (uint32_t)(((wm + mt*16 + a_row)*PAD + kofs + a_col) * 2)); \
            _Pragma("unroll")                                                   \
            for (int p = 0; p < 2; p++)                                         \
                ldsm4(bh_[p], sst + (uint32_t)((AELE + (wn + p*16 + b_row)*PAD + kofs + b_col) * 2)); \
            _Pragma("unroll")                                                   \
            for (int mt = 0; mt < 2; mt++)                                      \
            _Pragma("unroll")                                                   \
                for (int p = 0; p < 2; p++) {                                   \
                    mma16816h(acc[mt][2*p],   a_[mt], &bh_[p][0]);              \
                    mma16816h(acc[mt][2*p+1], a_[mt], &bh_[p][2]);              \
                }                                                               \
        }                                                                       \
        __syncthreads();                                                        \
    }

// ---------------- merged QKV GEMM with fused norm/rope/split epilogue --------
// grid (32, MROWS/64): bx 0-15 -> Q head, 16-23 -> K head, 24-31 -> V head.
__global__ __launch_bounds__(256, 3) void gemm_qkv(
    const __half* __restrict__ gA,
    const __half* __restrict__ Wqh_, const __half* __restrict__ Wkh_,
    const __half* __restrict__ Wvh_,
    bf16* __restrict__ Qh, bf16* __restrict__ Ql,
    bf16* __restrict__ Kh, bf16* __restrict__ Kl,
    __half* __restrict__ Vh,
    const float* __restrict__ q_scale, const float* __restrict__ k_scale,
    const float* __restrict__ cosT, const float* __restrict__ sinT)
{
    extern __shared__ __half sm[];
    const uint32_t sbase = (uint32_t)__cvta_generic_to_shared(sm);
    const int bx = blockIdx.x;
    const int row0 = blockIdx.y * 64;
    const int K = DD;
    const int niter = K / BKC;

    int mode, hloc;
    const __half* gB0;
    if (bx < 16)      { mode = 0; hloc = bx;      gB0 = Wqh_; }
    else if (bx < 24) { mode = 1; hloc = bx - 16; gB0 = Wkh_; }
    else              { mode = 2; hloc = bx - 24; gB0 = Wvh_; }
    const int col0 = hloc * 128;

    GEMM_PROLOGUE();
    GEMM_MAINLOOP1();

    // ---- stage fp32 tile into smem (reuse pipeline smem) ----
    float* sf = (float*)sm;                 // 64 x 132 floats = 33792 B <= 55296
    const int gr = lane >> 2, gc = (lane & 3) * 2;
#pragma unroll
    for (int mt = 0; mt < 2; mt++)
#pragma unroll
        for (int nt = 0; nt < 4; nt++) {
            int row = wm + mt*16 + gr;
            int col = wn + nt*8 + gc;
            *(float2*)&sf[(size_t)row*132 + col]     = make_float2(acc[mt][nt][0], acc[mt][nt][1]);
            *(float2*)&sf[(size_t)(row+8)*132 + col] = make_float2(acc[mt][nt][2], acc[mt][nt][3]);
        }
    __syncthreads();

    const float* scv = (mode == 0) ? q_scale : k_scale;
    const float smul = (mode == 0) ? QSCALE : 1.0f;
    const int   Hn   = (mode == 0) ? HQ : HKV;
    bf16* outh = (mode == 0) ? Qh : Kh;
    bf16* outl = (mode == 0) ? Ql : Kl;

    float4 sc4 = make_float4(1.f,1.f,1.f,1.f);
    if (mode < 2) sc4 = *(const float4*)&scv[lane*4];

    for (int rr = 0; rr < 8; rr++) {
        const int row  = wid*8 + rr;
        const int gtok = row0 + row;
        const int b = gtok >> 11, t = gtok & (TT-1);
        float4 v = *(float4*)&sf[(size_t)row*132 + lane*4];
        v.x *= INV256; v.y *= INV256; v.z *= INV256; v.w *= INV256;   // weight descale
        if (mode < 2) {
            float ss = v.x*v.x + v.y*v.y + v.z*v.z + v.w*v.w;
#pragma unroll
            for (int ofs = 16; ofs > 0; ofs >>= 1)
                ss += __shfl_xor_sync(0xffffffffu, ss, ofs);
            float inv = rsqrtf(ss*(1.0f/HD) + 1e-6f);
            v.x *= inv*sc4.x; v.y *= inv*sc4.y; v.z *= inv*sc4.z; v.w *= inv*sc4.w;
            float px = __shfl_xor_sync(0xffffffffu, v.x, 16);
            float py = __shfl_xor_sync(0xffffffffu, v.y, 16);
            float pz = __shfl_xor_sync(0xffffffffu, v.z, 16);
            float pw = __shfl_xor_sync(0xffffffffu, v.w, 16);
            float s = (lane < 16) ? -1.f : 1.f;
            float4 cs = *(const float4*)&cosT[(size_t)t*HD + lane*4];
            float4 sn = *(const float4*)&sinT[(size_t)t*HD + lane*4];
            float4 o;
            o.x = (v.x*cs.x + s*px*sn.x) * smul;
            o.y = (v.y*cs.y + s*py*sn.y) * smul;
            o.z = (v.z*cs.z + s*pz*sn.z) * smul;
            o.w = (v.w*cs.w + s*pw*sn.w) * smul;
            uint32_t H0, L0, H1, L1;
            split2(o.x, o.y, H0, L0);
            split2(o.z, o.w, H1, L1);
            size_t off = (((size_t)(b*Hn + hloc))*TT + t)*HD + lane*4;
            *(uint2*)&outh[off] = make_uint2(H0, H1);
            *(uint2*)&outl[off] = make_uint2(L0, L1);
        } else {
            size_t off = (size_t)gtok*(HKV*HD) + hloc*HD + lane*4;
            *(uint2*)&Vh[off] = make_uint2(packh(v.x, v.y), packh(v.z, v.w));
        }
    }
}

// ---------------- O-projection GEMM (1-plane weights, fp32 epilogue) ---------
// grid (DD/128, MROWS/64)
__global__ __launch_bounds__(256, 3) void gemm_o(
    const __half* __restrict__ gA,
    const __half* __restrict__ gB0,
    float* __restrict__ C, int N)
{
    extern __shared__ __half sm[];
    const uint32_t sbase = (uint32_t)__cvta_generic_to_shared(sm);
    const int row0 = blockIdx.y * 64, col0 = blockIdx.x * 128;
    const int K = DD;
    const int niter = K / BKC;

    GEMM_PROLOGUE();
    GEMM_MAINLOOP1();

    const int gr = lane >> 2, gc = (lane & 3) * 2;
#pragma unroll
    for (int mt = 0; mt < 2; mt++)
#pragma unroll
        for (int nt = 0; nt < 4; nt++) {
            int row = row0 + wm + mt*16 + gr;
            int col = col0 + wn + nt*8 + gc;
            *(float2*)&C[(size_t)row*N + col]     = make_float2(acc[mt][nt][0]*INV256, acc[mt][nt][1]*INV256);
            *(float2*)&C[(size_t)(row+8)*N + col] = make_float2(acc[mt][nt][2]*INV256, acc[mt][nt][3]*INV256);
        }
}

// ---------------- fused flash attention -------------------------------------
// QK^T: bf16x3 (accuracy-critical). PV: fp16 1-mma (P and V single planes).
// 3-stage KV pipeline, single barrier per tile, warp-level masked-tile skip.
#define BQ 128
#define BK 64
#define FP 136
#define QELE (BQ*FP)
#define KELE (BK*FP)
#define QAREA (2*QELE)
#define STGKV (3*KELE)
#define FLASH_SMEM ((QAREA + 3*STGKV) * 2)   // 226304 bytes

__global__ __launch_bounds__(256) void flash_kernel(
    const bf16* __restrict__ Qh, const bf16* __restrict__ Ql,
    const bf16* __restrict__ Kh, const bf16* __restrict__ Kl,
    const __half* __restrict__ Vh,
    __half* __restrict__ ctxh)
{
    extern __shared__ bf16 smf[];
    const int tid = threadIdx.x, lane = tid & 31, wid = tid >> 5;
    const int qb = gridDim.x - 1 - blockIdx.x;
    const int bh = blockIdx.y;
    const int b = bh >> 4, h = bh & 15, kv = h >> 1;
    const int q0 = qb * BQ;
    const uint32_t sbase = (uint32_t)__cvta_generic_to_shared(smf);

    const bf16* Qhg = Qh + ((size_t)(b*HQ  + h )*TT + q0)*HD;
    const bf16* Qlg = Ql + ((size_t)(b*HQ  + h )*TT + q0)*HD;
    const bf16* Khg = Kh + ((size_t)(b*HKV + kv)*TT)*HD;
    const bf16* Klg = Kl + ((size_t)(b*HKV + kv)*TT)*HD;
    const __half* Vhg = Vh + (size_t)b*TT*(HKV*HD) + kv*HD;

#pragma unroll
    for (int i = 0; i < 8; i++) {
        int c = tid + i*256;
        int row = c >> 4, col = (c & 15) * 8;
        cp_async16(sbase + (uint32_t)((row*FP + col) * 2),        Qhg + (size_t)row*HD + col);
        cp_async16(sbase + (uint32_t)((QELE + row*FP + col) * 2), Qlg + (size_t)row*HD + col);
    }

#define ISSUEKV(kt, stage) do {                                                     \
    const int k0_ = (kt) * BK;                                                      \
    const uint32_t kb_ = sbase + (uint32_t)((QAREA + (stage)*STGKV) * 2);           \
    _Pragma("unroll")                                                               \
    for (int i_ = 0; i_ < 4; i_++) {                                                \
        int c_ = tid + i_*256;                                                      \
        int row_ = c_ >> 4, col_ = (c_ & 15) * 8;                                   \
        uint32_t so_ = (uint32_t)((row_*FP + col_) * 2);                            \
        cp_async16(kb_ + so_,            Khg + (size_t)(k0_+row_)*HD + col_);       \
        cp_async16(kb_ + KELE*2 + so_,   Klg + (size_t)(k0_+row_)*HD + col_);       \
        cp_async16(kb_ + 2*KELE*2 + so_, Vhg + (size_t)(k0_+row_)*(HKV*HD) + col_); \
    }                                                                               \
} while (0)

    const int nkt = 2*qb + 2;
    ISSUEKV(0, 0);
    cp_commit();
    ISSUEKV(1, 1);
    cp_commit();

    const int r   = lane & 7, blkid = lane >> 3;
    const int a_row = ((blkid & 1) << 3) + r;
    const int a_col = (blkid >> 1) << 3;
    const int b_row = ((blkid >> 1) << 3) + r;
    const int b_col = (blkid & 1) << 3;
    const int gr = lane >> 2;

    float oacc[16][4];
#pragma unroll
    for (int i = 0; i < 16; i++)
#pragma unroll
        for (int j = 0; j < 4; j++) oacc[i][j] = 0.f;
    float m0 = -1e30f, m1 = -1e30f, l0 = 0.f, l1 = 0.f;

    const int row0g = q0 + wid*16 + gr;
    const int row1g = row0g + 8;
    const int rowmin = q0 + wid*16;
    const int rowmax = q0 + wid*16 + 15;

    int stg = 0;
    for (int kt = 0; kt < nkt; kt++) {
        if (kt + 1 < nkt) {
            asm volatile("cp.async.wait_group 1;\n" ::: "memory");
        } else {
            asm volatile("cp.async.wait_group 0;\n" ::: "memory");
        }
        __syncthreads();
        if (kt + 2 < nkt) {
            int s2 = stg + 2; if (s2 >= 3) s2 -= 3;
            ISSUEKV(kt + 2, s2);
            cp_commit();
        }

        const int k0 = kt * BK;
        const uint32_t kb_s = sbase + (uint32_t)((QAREA + stg*STGKV) * 2);

        // warp-level skip: whole 16-row warp slab above causal boundary
        if (k0 <= rowmax) {

        float sacc[8][4];
#pragma unroll
        for (int i = 0; i < 8; i++)
#pragma unroll
            for (int j = 0; j < 4; j++) sacc[i][j] = 0.f;

#pragma unroll
        for (int ks = 0; ks < 8; ks++) {
            uint32_t qa = sbase + (uint32_t)(((wid*16 + a_row)*FP + ks*16 + a_col) * 2);
            uint32_t qh[4], ql[4];
            ldsm4(qh, qa);
            ldsm4(ql, qa + QELE*2);
#pragma unroll
            for (int np = 0; np < 4; np++) {
                uint32_t ka = kb_s + (uint32_t)(((np*16 + b_row)*FP + ks*16 + b_col) * 2);
                uint32_t kh[4], kl[4];
                ldsm4(kh, ka);
                ldsm4(kl, ka + KELE*2);
                mma16816(sacc[2*np],   qh, &kh[0]);
                mma16816(sacc[2*np+1], qh, &kh[2]);
                mma16816(sacc[2*np],   qh, &kl[0]);
                mma16816(sacc[2*np+1], qh, &kl[2]);
                mma16816(sacc[2*np],   ql, &kh[0]);
                mma16816(sacc[2*np+1], ql, &kh[2]);
            }
        }

        // ---- causal mask (only near diagonal) + online softmax ----
        float mx0 = -1e30f, mx1 = -1e30f;
        if (k0 + 63 > rowmin) {
#pragma unroll
            for (int nt = 0; nt < 8; nt++) {
                int cg = k0 + nt*8 + (lane & 3)*2;
                if (cg     > row0g) sacc[nt][0] = -1e30f;
                if (cg + 1 > row0g) sacc[nt][1] = -1e30f;
                if (cg     > row1g) sacc[nt][2] = -1e30f;
                if (cg + 1 > row1g) sacc[nt][3] = -1e30f;
                mx0 = fmaxf(mx0, fmaxf(sacc[nt][0], sacc[nt][1]));
                mx1 = fmaxf(mx1, fmaxf(sacc[nt][2], sacc[nt][3]));
            }
        } else {
#pragma unroll
            for (int nt = 0; nt < 8; nt++) {
                mx0 = fmaxf(mx0, fmaxf(sacc[nt][0], sacc[nt][1]));
                mx1 = fmaxf(mx1, fmaxf(sacc[nt][2], sacc[nt][3]));
            }
        }
        mx0 = fmaxf(mx0, __shfl_xor_sync(0xffffffffu, mx0, 1));
        mx0 = fmaxf(mx0, __shfl_xor_sync(0xffffffffu, mx0, 2));
        mx1 = fmaxf(mx1, __shfl_xor_sync(0xffffffffu, mx1, 1));
        mx1 = fmaxf(mx1, __shfl_xor_sync(0xffffffffu, mx1, 2));

        float mn0 = fmaxf(m0, mx0), mn1 = fmaxf(m1, mx1);
        float sc0 = exp2f(m0 - mn0), sc1 = exp2f(m1 - mn1);
        m0 = mn0; m1 = mn1;

        float s0 = 0.f, s1 = 0.f;
#pragma unroll
        for (int nt = 0; nt < 8; nt++) {
            sacc[nt][0] = exp2f(sacc[nt][0] - m0);
            sacc[nt][1] = exp2f(sacc[nt][1] - m0);
            sacc[nt][2] = exp2f(sacc[nt][2] - m1);
            sacc[nt][3] = exp2f(sacc[nt][3] - m1);
            s0 += sacc[nt][0] + sacc[nt][1];
            s1 += sacc[nt][2] + sacc[nt][3];
        }
        s0 += __shfl_xor_sync(0xffffffffu, s0, 1);
        s0 += __shfl_xor_sync(0xffffffffu, s0, 2);
        s1 += __shfl_xor_sync(0xffffffffu, s1, 1);
        s1 += __shfl_xor_sync(0xffffffffu, s1, 2);
        l0 = l0*sc0 + s0;
        l1 = l1*sc1 + s1;

#pragma unroll
        for (int i = 0; i < 16; i++) {
            oacc[i][0] *= sc0; oacc[i][1] *= sc0;
            oacc[i][2] *= sc1; oacc[i][3] *= sc1;
        }

        // ---- O += P V (fp16 1-mma: P and V single planes) ----
        const int vrow = (lane & 7) + ((lane >> 3) & 1)*8;
        const int vcolb = ((lane >> 4) << 3);
#pragma unroll
        for (int kp = 0; kp < 4; kp++) {
            uint32_t ph[4];
#pragma unroll
            for (int half = 0; half < 2; half++) {
                ph[2*half]   = packh(sacc[2*kp+half][0], sacc[2*kp+half][1]);
                ph[2*half+1] = packh(sacc[2*kp+half][2], sacc[2*kp+half][3]);
            }
#pragma unroll
            for (int np = 0; np < 8; np++) {
                uint32_t va = kb_s + (uint32_t)((2*KELE + (kp*16 + vrow)*FP + np*16 + vcolb) * 2);
                uint32_t vh[4];
                ldsm4t(vh, va);
                mma16816h(oacc[2*np],   ph, &vh[0]);
                mma16816h(oacc[2*np+1], ph, &vh[2]);
            }
        }

        }  // end warp-skip

        if (++stg == 3) stg = 0;
    }
#undef ISSUEKV

    // ---- epilogue: O /= l, write ctx fp16 single plane ----
    const float il0 = 1.f / l0, il1 = 1.f / l1;
    const size_t tok0 = (size_t)(b*TT + q0 + wid*16 + gr);
#pragma unroll
    for (int nt = 0; nt < 16; nt++) {
        int col = h*HD + nt*8 + (lane & 3)*2;
        *(uint32_t*)&ctxh[tok0*(HQ*HD) + col]     = packh(oacc[nt][0]*il0, oacc[nt][1]*il0);
        *(uint32_t*)&ctxh[(tok0+8)*(HQ*HD) + col] = packh(oacc[nt][2]*il1, oacc[nt][3]*il1);
    }
}

// ---------------- launch ------------------------------------------------------
extern "C" void kernel_launch(void* const* d_in, const int* in_sizes, int n_in,
                              void* d_out, int out_size)
{
    const float* x       = (const float*)d_in[0];
    const float* cosT    = (const float*)d_in[2];
    const float* sinT    = (const float*)d_in[3];
    const float* Wq      = (const float*)d_in[4];
    const float* Wk      = (const float*)d_in[5];
    const float* Wv      = (const float*)d_in[6];
    const float* Wo      = (const float*)d_in[7];
    const float* q_scale = (const float*)d_in[8];
    const float* k_scale = (const float*)d_in[9];
    float* out = (float*)d_out;

    __half *xh,*Wqh,*Wkh,*Wvh,*Woh,*ctxh,*Vh;
    bf16 *Qh,*Ql,*Kh,*Kl;
    cudaGetSymbolAddress((void**)&xh,   g_xh);
    cudaGetSymbolAddress((void**)&Wqh,  g_Wqh);
    cudaGetSymbolAddress((void**)&Wkh,  g_Wkh);
    cudaGetSymbolAddress((void**)&Wvh,  g_Wvh);
    cudaGetSymbolAddress((void**)&Woh,  g_Woh);
    cudaGetSymbolAddress((void**)&Qh,   g_Qh);   cudaGetSymbolAddress((void**)&Ql,   g_Ql);
    cudaGetSymbolAddress((void**)&Kh,   g_Kh);   cudaGetSymbolAddress((void**)&Kl,   g_Kl);
    cudaGetSymbolAddress((void**)&Vh,   g_Vh);
    cudaGetSymbolAddress((void**)&ctxh, g_ctxh);

    static bool attr_set = false;
    if (!attr_set) {
        cudaFuncSetAttribute(gemm_qkv,     cudaFuncAttributeMaxDynamicSharedMemorySize, GSMEM2);
        cudaFuncSetAttribute(gemm_o,       cudaFuncAttributeMaxDynamicSharedMemorySize, GSMEM2);
        cudaFuncSetAttribute(flash_kernel, cudaFuncAttributeMaxDynamicSharedMemorySize, FLASH_SMEM);
        attr_set = true;
    }

    // 0: all operand conversions in one launch
    split_all_kernel<<<20480, 256>>>(
        (const float4*)x, (const float4*)Wq, (const float4*)Wk,
        (const float4*)Wv, (const float4*)Wo,
        xh, Wqh, Wkh, Wvh, Woh);

    // 1: merged QKV projection (fp16 1-mma, 64x128 CTA, 3 CTA/SM) + fused epilogue
    gemm_qkv<<<dim3(32, MROWS/64), 256, GSMEM2>>>(
        xh, Wqh, Wkh, Wvh,
        Qh, Ql, Kh, Kl, Vh, q_scale, k_scale, cosT, sinT);

    // 2: fused flash attention (QK bf16x3, PV fp16 1-mma, warp-skip)
    flash_kernel<<<dim3(TT/BQ, BB*HQ), 256, FLASH_SMEM>>>(Qh, Ql, Kh, Kl, Vh, ctxh);

    // 3: output projection (fp16 1-mma, 64x128 CTA, 3 CTA/SM, descale)
    gemm_o<<<dim3(DD/128, MROWS/64), 256, GSMEM2>>>(ctxh, Woh, out, DD);
}

// round 17
// speedup vs baseline: 1.0568x; 1.0568x over previous
#include <cuda_runtime.h>
#include <cuda_bf16.h>
#include <cuda_fp16.h>
#include <cstdint>
#include <cstddef>

// Problem constants
#define BB 2
#define TT 2048
#define DD 2048
#define HQ 16
#define HKV 8
#define HD 128
#define MROWS (BB*TT)   // 4096

typedef __nv_bfloat16 bf16;

// log2(e)/sqrt(128)
#define QSCALE 0.12752551164384637f
#define WSCALE 256.0f
#define INV256 0.00390625f

// ---------------- scratch (static device globals) ---------------------------
__device__ __half g_xh [(size_t)MROWS*DD];                      // single plane
__device__ __half g_Wqh[(size_t)HQ*HD*DD];                      // single plane
__device__ __half g_Wkh[(size_t)HKV*HD*DD];                     // single plane
__device__ __half g_Wvh[(size_t)HKV*HD*DD];                     // single plane
__device__ __half g_Woh[(size_t)DD*HQ*HD];                      // single plane
__device__ bf16 g_Qh [(size_t)BB*HQ*TT*HD],  g_Ql [(size_t)BB*HQ*TT*HD];
__device__ bf16 g_Kh [(size_t)BB*HKV*TT*HD], g_Kl [(size_t)BB*HKV*TT*HD];
__device__ __half g_Vh [(size_t)MROWS*HKV*HD];                  // single plane
__device__ __half g_ctxh[(size_t)MROWS*HQ*HD];                  // single plane

// ---------------- PTX helpers ------------------------------------------------
__device__ __forceinline__ void ldsm4(uint32_t* r, uint32_t a) {
    asm volatile("ldmatrix.sync.aligned.m8n8.x4.shared.b16 {%0,%1,%2,%3}, [%4];\n"
        : "=r"(r[0]), "=r"(r[1]), "=r"(r[2]), "=r"(r[3]) : "r"(a));
}
__device__ __forceinline__ void ldsm4t(uint32_t* r, uint32_t a) {
    asm volatile("ldmatrix.sync.aligned.m8n8.x4.trans.shared.b16 {%0,%1,%2,%3}, [%4];\n"
        : "=r"(r[0]), "=r"(r[1]), "=r"(r[2]), "=r"(r[3]) : "r"(a));
}
__device__ __forceinline__ void mma16816(float* c, const uint32_t* a, const uint32_t* b) {
    asm volatile("mma.sync.aligned.m16n8k16.row.col.f32.bf16.bf16.f32 "
        "{%0,%1,%2,%3}, {%4,%5,%6,%7}, {%8,%9}, {%0,%1,%2,%3};\n"
        : "+f"(c[0]), "+f"(c[1]), "+f"(c[2]), "+f"(c[3])
        : "r"(a[0]), "r"(a[1]), "r"(a[2]), "r"(a[3]), "r"(b[0]), "r"(b[1]));
}
__device__ __forceinline__ void mma16816h(float* c, const uint32_t* a, const uint32_t* b) {
    asm volatile("mma.sync.aligned.m16n8k16.row.col.f32.f16.f16.f32 "
        "{%0,%1,%2,%3}, {%4,%5,%6,%7}, {%8,%9}, {%0,%1,%2,%3};\n"
        : "+f"(c[0]), "+f"(c[1]), "+f"(c[2]), "+f"(c[3])
        : "r"(a[0]), "r"(a[1]), "r"(a[2]), "r"(a[3]), "r"(b[0]), "r"(b[1]));
}
__device__ __forceinline__ void cp_async16(uint32_t dst, const void* src) {
    asm volatile("cp.async.cg.shared.global [%0], [%1], 16;\n" :: "r"(dst), "l"(src));
}
__device__ __forceinline__ void cp_commit() {
    asm volatile("cp.async.commit_group;\n" ::: "memory");
}
__device__ __forceinline__ uint32_t packbf(float a, float b) {
    __nv_bfloat162 t = __floats2bfloat162_rn(a, b);
    return *(uint32_t*)&t;
}
__device__ __forceinline__ uint32_t packh(float a, float b) {
    __half2 t = __floats2half2_rn(a, b);
    return *(uint32_t*)&t;
}
__device__ __forceinline__ void split2(float a, float b, uint32_t& h, uint32_t& l) {
    bf16 ha = __float2bfloat16(a), hb = __float2bfloat16(b);
    h = ((uint32_t)__bfloat16_as_ushort(hb) << 16) | (uint32_t)__bfloat16_as_ushort(ha);
    l = packbf(a - __bfloat162float(ha), b - __bfloat162float(hb));
}

// ---------------- fused operand conversion (single launch) -------------------
__global__ __launch_bounds__(256) void split_all_kernel(
    const float4* __restrict__ x,  const float4* __restrict__ Wq,
    const float4* __restrict__ Wk, const float4* __restrict__ Wv,
    const float4* __restrict__ Wo,
    __half* __restrict__ xh,
    __half* __restrict__ Wqh, __half* __restrict__ Wkh,
    __half* __restrict__ Wvh, __half* __restrict__ Woh)
{
    int blk = blockIdx.x;
    if (blk < 8192) {
        int i = blk*256 + threadIdx.x;
        float4 v = x[i];
        *(uint2*)(xh + (size_t)i*4) = make_uint2(packh(v.x, v.y), packh(v.z, v.w));
        return;
    }
    blk -= 8192;
    const float4* in; __half* out;
    if (blk < 4096)      {                in = Wq; out = Wqh; }
    else if (blk < 6144) { blk -= 4096;   in = Wk; out = Wkh; }
    else if (blk < 8192) { blk -= 6144;   in = Wv; out = Wvh; }
    else                 { blk -= 8192;   in = Wo; out = Woh; }
    int i = blk*256 + threadIdx.x;
    float4 v = in[i];
    *(uint2*)(out + (size_t)i*4) =
        make_uint2(packh(v.x*WSCALE, v.y*WSCALE), packh(v.z*WSCALE, v.w*WSCALE));
}

// ---------------- GEMM core macros (fp16 1-mma, BK=64, 3-stage) --------------
#define BKC 64
#define PAD 72
#define ARR (128*PAD)           // 9216 fp16
#define STG2 (2*ARR)            // 18432 fp16 = 36864 B / stage
#define GSMEM1 (3*STG2*2)       // 110592 bytes

#define GEMM_PROLOGUE()                                                         \
    const int tid  = threadIdx.x;                                               \
    const int lane = tid & 31, wid = tid >> 5;                                  \
    const int wm = (wid & 1) * 64;                                              \
    const int wn = (wid >> 1) * 32;                                             \
    const int mrow = tid >> 3;                                                  \
    const int ccol = (tid & 7) * 8;                                             \
    const int r_   = lane & 7, blk_ = lane >> 3;                                \
    const int a_row = ((blk_ & 1) << 3) + r_;                                   \
    const int a_col = (blk_ >> 1) << 3;                                         \
    const int b_row = ((blk_ >> 1) << 3) + r_;                                  \
    const int b_col = (blk_ & 1) << 3;                                          \
    float acc[4][4][4];                                                         \
    _Pragma("unroll") for (int i = 0; i < 4; i++)                               \
    _Pragma("unroll") for (int j = 0; j < 4; j++)                               \
    _Pragma("unroll") for (int k = 0; k < 4; k++) acc[i][j][k] = 0.f;

#define ISSUE1(it, stage) do {                                                  \
    const int k0_ = (it) * BKC;                                                 \
    uint32_t sst_ = sbase + (uint32_t)(stage) * (STG2 * 2);                     \
    _Pragma("unroll")                                                           \
    for (int rg_ = 0; rg_ < 4; rg_++) {                                         \
        int m_ = mrow + rg_ * 32;                                               \
        cp_async16(sst_ + (uint32_t)((m_*PAD + ccol) * 2),                      \
                   gA + (size_t)(row0 + m_) * K + k0_ + ccol);                  \
        cp_async16(sst_ + (uint32_t)((ARR + m_*PAD + ccol) * 2),                \
                   gB0 + (size_t)(col0 + m_) * K + k0_ + ccol);                 \
    }                                                                           \
} while (0)

#define GEMM_MAINLOOP1()                                                        \
    ISSUE1(0, 0);                                                               \
    cp_commit();                                                                \
    ISSUE1(1, 1);                                                               \
    cp_commit();                                                                \
    int stg = 0;                                                                \
    for (int it = 0; it < niter; it++) {                                        \
        if (it + 1 < niter) {                                                   \
            asm volatile("cp.async.wait_group 1;\n" ::: "memory");              \
        } else {                                                                \
            asm volatile("cp.async.wait_group 0;\n" ::: "memory");              \
        }                                                                       \
        __syncthreads();                                                        \
        if (it + 2 < niter) {                                                   \
            int s2 = stg + 2; if (s2 >= 3) s2 -= 3;                             \
            ISSUE1(it + 2, s2);                                                 \
            cp_commit();                                                        \
        }                                                                       \
        const uint32_t sst = sbase + (uint32_t)stg * (STG2 * 2);                \
        _Pragma("unroll")                                                       \
        for (int ks = 0; ks < 4; ks++) {                                        \
            const int kofs = ks * 16;                                           \
            uint32_t a_[4][4], bh_[2][4];                                       \
            _Pragma("unroll")                                                   \
            for (int mt = 0; mt < 4; mt++)                                      \
                ldsm4(a_[mt], sst + (uint32_t)(((wm + mt*16 + a_row)*PAD + kofs + a_col) * 2)); \
            _Pragma("unroll")                                                   \
            for (int p = 0; p < 2; p++)                                         \
                ldsm4(bh_[p], sst + (uint32_t)((ARR + (wn + p*16 + b_row)*PAD + kofs + b_col) * 2)); \
            _Pragma("unroll")                                                   \
            for (int mt = 0; mt < 4; mt++)                                      \
            _Pragma("unroll")                                                   \
                for (int p = 0; p < 2; p++) {                                   \
                    mma16816h(acc[mt][2*p],   a_[mt], &bh_[p][0]);              \
                    mma16816h(acc[mt][2*p+1], a_[mt], &bh_[p][2]);              \
                }                                                               \
        }                                                                       \
        if (++stg == 3) stg = 0;                                                \
    }

// ---------------- merged QKV GEMM with fused norm/rope/split epilogue --------
__global__ __launch_bounds__(256, 2) void gemm_qkv(
    const __half* __restrict__ gA,
    const __half* __restrict__ Wqh_, const __half* __restrict__ Wkh_,
    const __half* __restrict__ Wvh_,
    bf16* __restrict__ Qh, bf16* __restrict__ Ql,
    bf16* __restrict__ Kh, bf16* __restrict__ Kl,
    __half* __restrict__ Vh,
    const float* __restrict__ q_scale, const float* __restrict__ k_scale,
    const float* __restrict__ cosT, const float* __restrict__ sinT)
{
    extern __shared__ __half sm[];
    const uint32_t sbase = (uint32_t)__cvta_generic_to_shared(sm);
    const int bx = blockIdx.x;
    const int row0 = blockIdx.y * 128;
    const int K = DD;
    const int niter = K / BKC;

    int mode, hloc;
    const __half* gB0;
    if (bx < 16)      { mode = 0; hloc = bx;      gB0 = Wqh_; }
    else if (bx < 24) { mode = 1; hloc = bx - 16; gB0 = Wkh_; }
    else              { mode = 2; hloc = bx - 24; gB0 = Wvh_; }
    const int col0 = hloc * 128;

    GEMM_PROLOGUE();
    GEMM_MAINLOOP1();

    // ---- stage fp32 tile into smem (reuse pipeline smem) ----
    __syncthreads();
    float* sf = (float*)sm;                 // 128 x 132 floats = 67584 B <= 110592
    const int gr = lane >> 2, gc = (lane & 3) * 2;
#pragma unroll
    for (int mt = 0; mt < 4; mt++)
#pragma unroll
        for (int nt = 0; nt < 4; nt++) {
            int row = wm + mt*16 + gr;
            int col = wn + nt*8 + gc;
            *(float2*)&sf[(size_t)row*132 + col]     = make_float2(acc[mt][nt][0], acc[mt][nt][1]);
            *(float2*)&sf[(size_t)(row+8)*132 + col] = make_float2(acc[mt][nt][2], acc[mt][nt][3]);
        }
    __syncthreads();

    const float* scv = (mode == 0) ? q_scale : k_scale;
    const float smul = (mode == 0) ? QSCALE : 1.0f;
    const int   Hn   = (mode == 0) ? HQ : HKV;
    bf16* outh = (mode == 0) ? Qh : Kh;
    bf16* outl = (mode == 0) ? Ql : Kl;

    float4 sc4 = make_float4(1.f,1.f,1.f,1.f);
    if (mode < 2) sc4 = *(const float4*)&scv[lane*4];

    for (int rr = 0; rr < 16; rr++) {
        const int row  = wid*16 + rr;
        const int gtok = row0 + row;
        const int b = gtok >> 11, t = gtok & (TT-1);
        float4 v = *(float4*)&sf[(size_t)row*132 + lane*4];
        v.x *= INV256; v.y *= INV256; v.z *= INV256; v.w *= INV256;   // weight descale
        if (mode < 2) {
            float ss = v.x*v.x + v.y*v.y + v.z*v.z + v.w*v.w;
#pragma unroll
            for (int ofs = 16; ofs > 0; ofs >>= 1)
                ss += __shfl_xor_sync(0xffffffffu, ss, ofs);
            float inv = rsqrtf(ss*(1.0f/HD) + 1e-6f);
            v.x *= inv*sc4.x; v.y *= inv*sc4.y; v.z *= inv*sc4.z; v.w *= inv*sc4.w;
            float px = __shfl_xor_sync(0xffffffffu, v.x, 16);
            float py = __shfl_xor_sync(0xffffffffu, v.y, 16);
            float pz = __shfl_xor_sync(0xffffffffu, v.z, 16);
            float pw = __shfl_xor_sync(0xffffffffu, v.w, 16);
            float s = (lane < 16) ? -1.f : 1.f;
            float4 cs = *(const float4*)&cosT[(size_t)t*HD + lane*4];
            float4 sn = *(const float4*)&sinT[(size_t)t*HD + lane*4];
            float4 o;
            o.x = (v.x*cs.x + s*px*sn.x) * smul;
            o.y = (v.y*cs.y + s*py*sn.y) * smul;
            o.z = (v.z*cs.z + s*pz*sn.z) * smul;
            o.w = (v.w*cs.w + s*pw*sn.w) * smul;
            uint32_t H0, L0, H1, L1;
            split2(o.x, o.y, H0, L0);
            split2(o.z, o.w, H1, L1);
            size_t off = (((size_t)(b*Hn + hloc))*TT + t)*HD + lane*4;
            *(uint2*)&outh[off] = make_uint2(H0, H1);
            *(uint2*)&outl[off] = make_uint2(L0, L1);
        } else {
            size_t off = (size_t)gtok*(HKV*HD) + hloc*HD + lane*4;
            *(uint2*)&Vh[off] = make_uint2(packh(v.x, v.y), packh(v.z, v.w));
        }
    }
}

// ---------------- O-projection GEMM (1-plane weights, fp32 epilogue) ---------
__global__ __launch_bounds__(256, 2) void gemm_o(
    const __half* __restrict__ gA,
    const __half* __restrict__ gB0,
    float* __restrict__ C, int N)
{
    extern __shared__ __half sm[];
    const uint32_t sbase = (uint32_t)__cvta_generic_to_shared(sm);
    const int row0 = blockIdx.y * 128, col0 = blockIdx.x * 128;
    const int K = DD;
    const int niter = K / BKC;

    GEMM_PROLOGUE();
    GEMM_MAINLOOP1();

    const int gr = lane >> 2, gc = (lane & 3) * 2;
#pragma unroll
    for (int mt = 0; mt < 4; mt++)
#pragma unroll
        for (int nt = 0; nt < 4; nt++) {
            int row = row0 + wm + mt*16 + gr;
            int col = col0 + wn + nt*8 + gc;
            *(float2*)&C[(size_t)row*N + col]     = make_float2(acc[mt][nt][0]*INV256, acc[mt][nt][1]*INV256);
            *(float2*)&C[(size_t)(row+8)*N + col] = make_float2(acc[mt][nt][2]*INV256, acc[mt][nt][3]*INV256);
        }
}

// ---------------- fused flash attention -------------------------------------
// QK^T: bf16x3 (accuracy-critical). PV: fp16 1-mma (P and V single planes).
// 3-stage KV pipeline, single barrier per tile, warp-level masked-tile skip.
#define BQ 128
#define BK 64
#define FP 136
#define QELE (BQ*FP)
#define KELE (BK*FP)
#define QAREA (2*QELE)
#define STGKV (3*KELE)
#define FLASH_SMEM ((QAREA + 3*STGKV) * 2)   // 226304 bytes

__global__ __launch_bounds__(256) void flash_kernel(
    const bf16* __restrict__ Qh, const bf16* __restrict__ Ql,
    const bf16* __restrict__ Kh, const bf16* __restrict__ Kl,
    const __half* __restrict__ Vh,
    __half* __restrict__ ctxh)
{
    extern __shared__ bf16 smf[];
    const int tid = threadIdx.x, lane = tid & 31, wid = tid >> 5;
    const int qb = gridDim.x - 1 - blockIdx.x;
    const int bh = blockIdx.y;
    const int b = bh >> 4, h = bh & 15, kv = h >> 1;
    const int q0 = qb * BQ;
    const uint32_t sbase = (uint32_t)__cvta_generic_to_shared(smf);

    const bf16* Qhg = Qh + ((size_t)(b*HQ  + h )*TT + q0)*HD;
    const bf16* Qlg = Ql + ((size_t)(b*HQ  + h )*TT + q0)*HD;
    const bf16* Khg = Kh + ((size_t)(b*HKV + kv)*TT)*HD;
    const bf16* Klg = Kl + ((size_t)(b*HKV + kv)*TT)*HD;
    const __half* Vhg = Vh + (size_t)b*TT*(HKV*HD) + kv*HD;

#pragma unroll
    for (int i = 0; i < 8; i++) {
        int c = tid + i*256;
        int row = c >> 4, col = (c & 15) * 8;
        cp_async16(sbase + (uint32_t)((row*FP + col) * 2),        Qhg + (size_t)row*HD + col);
        cp_async16(sbase + (uint32_t)((QELE + row*FP + col) * 2), Qlg + (size_t)row*HD + col);
    }

#define ISSUEKV(kt, stage) do {                                                     \
    const int k0_ = (kt) * BK;                                                      \
    const uint32_t kb_ = sbase + (uint32_t)((QAREA + (stage)*STGKV) * 2);           \
    _Pragma("unroll")                                                               \
    for (int i_ = 0; i_ < 4; i_++) {                                                \
        int c_ = tid + i_*256;                                                      \
        int row_ = c_ >> 4, col_ = (c_ & 15) * 8;                                   \
        uint32_t so_ = (uint32_t)((row_*FP + col_) * 2);                            \
        cp_async16(kb_ + so_,            Khg + (size_t)(k0_+row_)*HD + col_);       \
        cp_async16(kb_ + KELE*2 + so_,   Klg + (size_t)(k0_+row_)*HD + col_);       \
        cp_async16(kb_ + 2*KELE*2 + so_, Vhg + (size_t)(k0_+row_)*(HKV*HD) + col_); \
    }                                                                               \
} while (0)

    const int nkt = 2*qb + 2;
    ISSUEKV(0, 0);
    cp_commit();
    ISSUEKV(1, 1);
    cp_commit();

    const int r   = lane & 7, blkid = lane >> 3;
    const int a_row = ((blkid & 1) << 3) + r;
    const int a_col = (blkid >> 1) << 3;
    const int b_row = ((blkid >> 1) << 3) + r;
    const int b_col = (blkid & 1) << 3;
    const int gr = lane >> 2;

    float oacc[16][4];
#pragma unroll
    for (int i = 0; i < 16; i++)
#pragma unroll
        for (int j = 0; j < 4; j++) oacc[i][j] = 0.f;
    float m0 = -1e30f, m1 = -1e30f, l0 = 0.f, l1 = 0.f;

    const int row0g = q0 + wid*16 + gr;
    const int row1g = row0g + 8;
    const int rowmin = q0 + wid*16;
    const int rowmax = q0 + wid*16 + 15;

    int stg = 0;
    for (int kt = 0; kt < nkt; kt++) {
        if (kt + 1 < nkt) {
            asm volatile("cp.async.wait_group 1;\n" ::: "memory");
        } else {
            asm volatile("cp.async.wait_group 0;\n" ::: "memory");
        }
        __syncthreads();
        if (kt + 2 < nkt) {
            int s2 = stg + 2; if (s2 >= 3) s2 -= 3;
            ISSUEKV(kt + 2, s2);
            cp_commit();
        }

        const int k0 = kt * BK;
        const uint32_t kb_s = sbase + (uint32_t)((QAREA + stg*STGKV) * 2);

        // warp-level skip: this warp's 16-row slab entirely above the key range
        if (k0 <= rowmax) {

        float sacc[8][4];
#pragma unroll
        for (int i = 0; i < 8; i++)
#pragma unroll
            for (int j = 0; j < 4; j++) sacc[i][j] = 0.f;

#pragma unroll
        for (int ks = 0; ks < 8; ks++) {
            uint32_t qa = sbase + (uint32_t)(((wid*16 + a_row)*FP + ks*16 + a_col) * 2);
            uint32_t qh[4], ql[4];
            ldsm4(qh, qa);
            ldsm4(ql, qa + QELE*2);
#pragma unroll
            for (int np = 0; np < 4; np++) {
                uint32_t ka = kb_s + (uint32_t)(((np*16 + b_row)*FP + ks*16 + b_col) * 2);
                uint32_t kh[4], kl[4];
                ldsm4(kh, ka);
                ldsm4(kl, ka + KELE*2);
                mma16816(sacc[2*np],   qh, &kh[0]);
                mma16816(sacc[2*np+1], qh, &kh[2]);
                mma16816(sacc[2*np],   qh, &kl[0]);
                mma16816(sacc[2*np+1], qh, &kl[2]);
                mma16816(sacc[2*np],   ql, &kh[0]);
                mma16816(sacc[2*np+1], ql, &kh[2]);
            }
        }

        // ---- causal mask (only near diagonal) + online softmax ----
        float mx0 = -1e30f, mx1 = -1e30f;
        if (k0 + 63 > rowmin) {
#pragma unroll
            for (int nt = 0; nt < 8; nt++) {
                int cg = k0 + nt*8 + (lane & 3)*2;
                if (cg     > row0g) sacc[nt][0] = -1e30f;
                if (cg + 1 > row0g) sacc[nt][1] = -1e30f;
                if (cg     > row1g) sacc[nt][2] = -1e30f;
                if (cg + 1 > row1g) sacc[nt][3] = -1e30f;
                mx0 = fmaxf(mx0, fmaxf(sacc[nt][0], sacc[nt][1]));
                mx1 = fmaxf(mx1, fmaxf(sacc[nt][2], sacc[nt][3]));
            }
        } else {
#pragma unroll
            for (int nt = 0; nt < 8; nt++) {
                mx0 = fmaxf(mx0, fmaxf(sacc[nt][0], sacc[nt][1]));
                mx1 = fmaxf(mx1, fmaxf(sacc[nt][2], sacc[nt][3]));
            }
        }
        mx0 = fmaxf(mx0, __shfl_xor_sync(0xffffffffu, mx0, 1));
        mx0 = fmaxf(mx0, __shfl_xor_sync(0xffffffffu, mx0, 2));
        mx1 = fmaxf(mx1, __shfl_xor_sync(0xffffffffu, mx1, 1));
        mx1 = fmaxf(mx1, __shfl_xor_sync(0xffffffffu, mx1, 2));

        float mn0 = fmaxf(m0, mx0), mn1 = fmaxf(m1, mx1);
        float sc0 = exp2f(m0 - mn0), sc1 = exp2f(m1 - mn1);
        m0 = mn0; m1 = mn1;

        float s0 = 0.f, s1 = 0.f;
#pragma unroll
        for (int nt = 0; nt < 8; nt++) {
            sacc[nt][0] = exp2f(sacc[nt][0] - m0);
            sacc[nt][1] = exp2f(sacc[nt][1] - m0);
            sacc[nt][2] = exp2f(sacc[nt][2] - m1);
            sacc[nt][3] = exp2f(sacc[nt][3] - m1);
            s0 += sacc[nt][0] + sacc[nt][1];
            s1 += sacc[nt][2] + sacc[nt][3];
        }
        s0 += __shfl_xor_sync(0xffffffffu, s0, 1);
        s0 += __shfl_xor_sync(0xffffffffu, s0, 2);
        s1 += __shfl_xor_sync(0xffffffffu, s1, 1);
        s1 += __shfl_xor_sync(0xffffffffu, s1, 2);
        l0 = l0*sc0 + s0;
        l1 = l1*sc1 + s1;

#pragma unroll
        for (int i = 0; i < 16; i++) {
            oacc[i][0] *= sc0; oacc[i][1] *= sc0;
            oacc[i][2] *= sc1; oacc[i][3] *= sc1;
        }

        // ---- O += P V (fp16 1-mma: P and V single planes) ----
        const int vrow = (lane & 7) + ((lane >> 3) & 1)*8;
        const int vcolb = ((lane >> 4) << 3);
#pragma unroll
        for (int kp = 0; kp < 4; kp++) {
            uint32_t ph[4];
#pragma unroll
            for (int half = 0; half < 2; half++) {
                ph[2*half]   = packh(sacc[2*kp+half][0], sacc[2*kp+half][1]);
                ph[2*half+1] = packh(sacc[2*kp+half][2], sacc[2*kp+half][3]);
            }
#pragma unroll
            for (int np = 0; np < 8; np++) {
                uint32_t va = kb_s + (uint32_t)((2*KELE + (kp*16 + vrow)*FP + np*16 + vcolb) * 2);
                uint32_t vh[4];
                ldsm4t(vh, va);
                mma16816h(oacc[2*np],   ph, &vh[0]);
                mma16816h(oacc[2*np+1], ph, &vh[2]);
            }
        }

        }  // end warp-skip

        if (++stg == 3) stg = 0;
    }
#undef ISSUEKV

    // ---- epilogue: O /= l, write ctx fp16 single plane ----
    const float il0 = 1.f / l0, il1 = 1.f / l1;
    const size_t tok0 = (size_t)(b*TT + q0 + wid*16 + gr);
#pragma unroll
    for (int nt = 0; nt < 16; nt++) {
        int col = h*HD + nt*8 + (lane & 3)*2;
        *(uint32_t*)&ctxh[tok0*(HQ*HD) + col]     = packh(oacc[nt][0]*il0, oacc[nt][1]*il0);
        *(uint32_t*)&ctxh[(tok0+8)*(HQ*HD) + col] = packh(oacc[nt][2]*il1, oacc[nt][3]*il1);
    }
}

// ---------------- launch ------------------------------------------------------
extern "C" void kernel_launch(void* const* d_in, const int* in_sizes, int n_in,
                              void* d_out, int out_size)
{
    const float* x       = (const float*)d_in[0];
    const float* cosT    = (const float*)d_in[2];
    const float* sinT    = (const float*)d_in[3];
    const float* Wq      = (const float*)d_in[4];
    const float* Wk      = (const float*)d_in[5];
    const float* Wv      = (const float*)d_in[6];
    const float* Wo      = (const float*)d_in[7];
    const float* q_scale = (const float*)d_in[8];
    const float* k_scale = (const float*)d_in[9];
    float* out = (float*)d_out;

    __half *xh,*Wqh,*Wkh,*Wvh,*Woh,*ctxh,*Vh;
    bf16 *Qh,*Ql,*Kh,*Kl;
    cudaGetSymbolAddress((void**)&xh,   g_xh);
    cudaGetSymbolAddress((void**)&Wqh,  g_Wqh);
    cudaGetSymbolAddress((void**)&Wkh,  g_Wkh);
    cudaGetSymbolAddress((void**)&Wvh,  g_Wvh);
    cudaGetSymbolAddress((void**)&Woh,  g_Woh);
    cudaGetSymbolAddress((void**)&Qh,   g_Qh);   cudaGetSymbolAddress((void**)&Ql,   g_Ql);
    cudaGetSymbolAddress((void**)&Kh,   g_Kh);   cudaGetSymbolAddress((void**)&Kl,   g_Kl);
    cudaGetSymbolAddress((void**)&Vh,   g_Vh);
    cudaGetSymbolAddress((void**)&ctxh, g_ctxh);

    static bool attr_set = false;
    if (!attr_set) {
        cudaFuncSetAttribute(gemm_qkv,     cudaFuncAttributeMaxDynamicSharedMemorySize, GSMEM1);
        cudaFuncSetAttribute(gemm_o,       cudaFuncAttributeMaxDynamicSharedMemorySize, GSMEM1);
        cudaFuncSetAttribute(flash_kernel, cudaFuncAttributeMaxDynamicSharedMemorySize, FLASH_SMEM);
        attr_set = true;
    }

    // 0: all operand conversions in one launch
    split_all_kernel<<<20480, 256>>>(
        (const float4*)x, (const float4*)Wq, (const float4*)Wk,
        (const float4*)Wv, (const float4*)Wo,
        xh, Wqh, Wkh, Wvh, Woh);

    // 1: merged QKV projection (fp16 1-mma, BK=64, 128x128) + fused epilogue
    gemm_qkv<<<dim3(32, MROWS/128), 256, GSMEM1>>>(
        xh, Wqh, Wkh, Wvh,
        Qh, Ql, Kh, Kl, Vh, q_scale, k_scale, cosT, sinT);

    // 2: fused flash attention (QK bf16x3, PV fp16 1-mma, warp-skip)
    flash_kernel<<<dim3(TT/BQ, BB*HQ), 256, FLASH_SMEM>>>(Qh, Ql, Kh, Kl, Vh, ctxh);

    // 3: output projection (fp16 1-mma, BK=64, 128x128, descale)
    gemm_o<<<dim3(DD/128, MROWS/128), 256, GSMEM1>>>(ctxh, Woh, out, DD);
}